// round 16
// baseline (speedup 1.0000x reference)
#include <cuda_runtime.h>
#include <cuda_fp16.h>
#include <cstdint>

// ---------------------------------------------------------------------------
// QuantizedD4Linear on GB300 (sm_103a; harness emits compute_103 base PTX so
// tcgen05 is unavailable -> mma.sync.m16n8k16 HMMA path)
//   out = fwht( fp16( fwht(x*SU)/1024 ) @ W^T  * Wscale*1024 ) * SV
//   W[m, 4j+t] = D4_CB[Qidxs[m,j], t]
// R15: GEMM = exact R7 skeleton (2 buffers, 64KB smem, 2 CTA/SM, same loader
//      addresses) with the 8 cp16/thread ISSUE moved inside the kk loop
//      (2 per K16 step, prefetching chunk c+1 into buf^1), one barrier per
//      chunk, cp_wait<0> at top. Targets the tensor-idle LDGSTS issue burst.
// ---------------------------------------------------------------------------

#define ROWS 8192   // 4*2048
#define DIN  4096   // 4*1024
#define MW   4096   // output features

// scratch (device globals: allocation-free rule)
static __device__ __half g_Xh[(size_t)ROWS * DIN];   // 64 MB fp16 activations
static __device__ __half g_W [(size_t)MW   * DIN];   // 32 MB fp16 decoded weights
static __device__ __half g_Zh[(size_t)ROWS * MW];    // 64 MB fp16 z (pre 2nd fwht)

// ---------------------------------------------------------------------------
// PTX helpers (base-ISA only: cp.async / ldmatrix / mma.sync)
// ---------------------------------------------------------------------------
static __device__ __forceinline__ uint32_t smem_u32(const void* p) {
    uint32_t a;
    asm("{ .reg .u64 t; cvta.to.shared.u64 t, %1; cvt.u32.u64 %0, t; }" : "=r"(a) : "l"(p));
    return a;
}
static __device__ __forceinline__ void cp16(uint32_t dst, const void* src) {
    asm volatile("cp.async.cg.shared.global [%0], [%1], 16;" :: "r"(dst), "l"(src) : "memory");
}
static __device__ __forceinline__ void cp_commit() {
    asm volatile("cp.async.commit_group;" ::: "memory");
}
template <int N>
static __device__ __forceinline__ void cp_wait() {
    asm volatile("cp.async.wait_group %0;" :: "n"(N) : "memory");
}
static __device__ __forceinline__ uint32_t sw128(uint32_t o) { return o ^ ((o >> 3) & 0x70); }

static __device__ __forceinline__ void ldsm4(uint32_t* r, uint32_t addr) {
    asm volatile("ldmatrix.sync.aligned.m8n8.x4.shared.b16 {%0,%1,%2,%3}, [%4];"
                 : "=r"(r[0]), "=r"(r[1]), "=r"(r[2]), "=r"(r[3]) : "r"(addr));
}
static __device__ __forceinline__ void mma16816(float* c, const uint32_t* a, const uint32_t* b) {
    asm volatile(
        "mma.sync.aligned.m16n8k16.row.col.f32.f16.f16.f32 "
        "{%0,%1,%2,%3}, {%4,%5,%6,%7}, {%8,%9}, {%0,%1,%2,%3};"
        : "+f"(c[0]), "+f"(c[1]), "+f"(c[2]), "+f"(c[3])
        : "r"(a[0]), "r"(a[1]), "r"(a[2]), "r"(a[3]), "r"(b[0]), "r"(b[1]));
}

// ---------------------------------------------------------------------------
// register-blocked FWHT helpers: 4096 = 16 x 16 x 16 radix decomposition
// ---------------------------------------------------------------------------
static __device__ __forceinline__ void fwht16(float* r) {
#pragma unroll
    for (int h = 1; h < 16; h <<= 1) {
#pragma unroll
        for (int j = 0; j < 16; j++) {
            if (!(j & h)) {
                float a = r[j], b = r[j + h];
                r[j] = a + b;
                r[j + h] = a - b;
            }
        }
    }
}
#define PAD(i) ((i) + ((i) >> 4))

// kernel 1: Xh = fp16( fwht(input*SU) / (64*1024) )
__global__ void __launch_bounds__(256) fwht_in_kernel(const float* __restrict__ in,
                                                      const float* __restrict__ SU) {
    __shared__ float s[4096 + 256];
    const int row = blockIdx.x;
    const int t = threadIdx.x;
    const float* xr = in + (size_t)row * DIN;
    float r[16];
#pragma unroll
    for (int q = 0; q < 4; q++) {
        float4 v = *(const float4*)(xr + t * 16 + q * 4);
        float4 u = *(const float4*)(SU + t * 16 + q * 4);
        r[q * 4 + 0] = v.x * u.x;
        r[q * 4 + 1] = v.y * u.y;
        r[q * 4 + 2] = v.z * u.z;
        r[q * 4 + 3] = v.w * u.w;
    }
    fwht16(r);                              // bits 0-3
#pragma unroll
    for (int j = 0; j < 16; j++) { int i = t * 16 + j; s[PAD(i)] = r[j]; }
    __syncthreads();
    const int ilo = t & 15, ihi = t >> 4;
#pragma unroll
    for (int j = 0; j < 16; j++) { int i = ilo + 16 * j + 256 * ihi; r[j] = s[PAD(i)]; }
    fwht16(r);                              // bits 4-7
#pragma unroll
    for (int j = 0; j < 16; j++) { int i = ilo + 16 * j + 256 * ihi; s[PAD(i)] = r[j]; }
    __syncthreads();
#pragma unroll
    for (int j = 0; j < 16; j++) { int i = t + 256 * j; r[j] = s[PAD(i)]; }
    fwht16(r);                              // bits 8-11
    const float sc = 1.0f / 65536.0f;       // (1/sqrt(4096)) * (1/1024)
    __half* orow = g_Xh + (size_t)row * DIN;
#pragma unroll
    for (int j = 0; j < 16; j++)
        orow[t + 256 * j] = __float2half_rn(r[j] * sc);
}

// ---------------------------------------------------------------------------
// kernel 2: decode W[m, 4j..4j+3] = CB[Qidxs[m,j]], runtime CB dtype detect
// ---------------------------------------------------------------------------
__global__ void __launch_bounds__(256) decode_kernel(const int* __restrict__ Qidxs,
                                                     const void* __restrict__ CBraw) {
    __shared__ uint2 cb[256];
    const int t = threadIdx.x;

    const uint32_t w0 = ((const uint32_t*)CBraw)[0];
    int mode;                                   // 0=f16, 1=bf16, 2=f32
    if ((w0 & 0xFFFFu) == 0u) {
        mode = 2;
    } else {
        const uint32_t h = w0 & 0x7FFFu;
        mode = (h == 0x3800u || h == 0x3E00u || h == 0x4100u) ? 0 : 1;
    }

    if (mode == 0) {
        cb[t] = ((const uint2*)CBraw)[t];       // 4 halfs, passthrough
    } else if (mode == 2) {
        float4 v = ((const float4*)CBraw)[t];   // 4 f32 per entry
        __half2 lo = __floats2half2_rn(v.x, v.y);
        __half2 hi = __floats2half2_rn(v.z, v.w);
        uint2 o;
        o.x = *(const uint32_t*)&lo;
        o.y = *(const uint32_t*)&hi;
        cb[t] = o;
    } else {
        uint2 v = ((const uint2*)CBraw)[t];     // 4 bf16 per entry
        uint32_t b0 = (v.x & 0xFFFFu) << 16, b1 = (v.x & 0xFFFF0000u);
        uint32_t b2 = (v.y & 0xFFFFu) << 16, b3 = (v.y & 0xFFFF0000u);
        __half2 lo = __floats2half2_rn(__uint_as_float(b0), __uint_as_float(b1));
        __half2 hi = __floats2half2_rn(__uint_as_float(b2), __uint_as_float(b3));
        uint2 o;
        o.x = *(const uint32_t*)&lo;
        o.y = *(const uint32_t*)&hi;
        cb[t] = o;
    }
    __syncthreads();

    const int idx = blockIdx.x * 256 + t;       // over 4096*1024 code positions
    const int q = Qidxs[idx];
    ((uint2*)g_W)[idx] = cb[q];                 // 8 bytes = 4 halfs
}

// dummy kernel: shifts the ncu capture window (-s 5 -c 1) onto gemm_kernel.
__global__ void dummy_kernel() {}

// ---------------------------------------------------------------------------
// kernel 3: HMMA GEMM  Zh = fp16( Xh @ W^T ), f32 accumulate
//   BM=128, BN=128, BK=64; 8 warps, warp tile 64x32 (R7 fragments)
//   2-buffer double buffer (R7 layout, 64 KB), cp.async issue interleaved
//   into the kk loop (2 cp16/thread/kk, chunk c+1 -> buf^1), commit after
//   the kk loop, cp_wait<0> + ONE __syncthreads at loop top. 2 CTAs/SM.
// ---------------------------------------------------------------------------
#define BK 64
#define NITER (DIN / BK)        // 64
#define ATILE_BYTES 16384       // 128 rows * 128 B

extern __shared__ char dynsmem[];

__global__ void __launch_bounds__(256, 2) gemm_kernel() {
    const uint32_t base = smem_u32(dynsmem);
    const uint32_t aA = base;                       // [A0][A1][B0][B1], 16KB each
    const uint32_t aB = base + 2 * ATILE_BYTES;

    const int t = threadIdx.x;
    const int wid = t >> 5;
    const int lane = t & 31;
    const int wm = (wid >> 2) * 64;                 // warp m offset in tile
    const int wn = (wid & 3) * 32;                  // warp n offset in tile

    const int m0 = blockIdx.y * 128;
    const int n0 = blockIdx.x * 128;
    const __half* Ag = g_Xh + (size_t)m0 * DIN;
    const __half* Bg = g_W + (size_t)n0 * DIN;

    float acc[4][4][4];
#pragma unroll
    for (int mi = 0; mi < 4; mi++)
#pragma unroll
        for (int nj = 0; nj < 4; nj++)
#pragma unroll
            for (int q = 0; q < 4; q++) acc[mi][nj][q] = 0.0f;

    // loader components (R7 mapping: op = t + 256*i -> full 128B rows)
    const int ld_row0 = t >> 3;                     // rows 0..31 (+32 per i)
    const int ld_seg = t & 7;
    const uint32_t ld_off0 = sw128((uint32_t)(ld_row0 * 128 + ld_seg * 16));
    const size_t ld_g0 = (size_t)ld_row0 * DIN + ld_seg * 8;

    // prologue: chunk 0 -> buf 0 (burst, one group)
    {
#pragma unroll
        for (int i = 0; i < 4; i++) {
            uint32_t off = ld_off0 + (uint32_t)i * 32 * 128;   // +32 rows per i
            size_t goff = ld_g0 + (size_t)i * 32 * DIN;
            cp16(aA + off, Ag + goff);
            cp16(aB + off, Bg + goff);
        }
        cp_commit();
    }

    // ldmatrix intra-warp address components
    const int a_r = (lane & 15);                    // A row within 16
    const int a_c = (lane >> 4) << 3;               // A col half-offset {0,8}
    const int b_r = (lane & 7) + ((lane >> 4) << 3);// B n-row within 16
    const int b_c = ((lane >> 3) & 1) << 3;         // B k-col offset {0,8}

#pragma unroll 1
    for (int c = 0; c < NITER; ++c) {
        const int buf = c & 1;

        cp_wait<0>();        // chunk c (issued during iteration c-1) resident
        __syncthreads();     // publishes cp.async writes to all threads; also
                             // proves every warp finished reading buf^1

        const uint32_t sA = aA + buf * ATILE_BYTES;
        const uint32_t sB = aB + buf * ATILE_BYTES;
        const uint32_t dA = aA + (buf ^ 1) * ATILE_BYTES;
        const uint32_t dB = aB + (buf ^ 1) * ATILE_BYTES;
        const bool pf = (c + 1 < NITER);
        const __half* ga = Ag + (c + 1) * BK;
        const __half* gb = Bg + (c + 1) * BK;

#pragma unroll
        for (int kk = 0; kk < 4; kk++) {            // K16 steps within BK=64
            uint32_t a[4][4], b[2][4];
#pragma unroll
            for (int mi = 0; mi < 4; mi++) {
                int row = wm + mi * 16 + a_r;
                int col = kk * 16 + a_c;
                ldsm4(a[mi], sA + sw128((uint32_t)(row * 128 + col * 2)));
            }
#pragma unroll
            for (int ni = 0; ni < 2; ni++) {
                int nrow = wn + ni * 16 + b_r;
                int kcol = kk * 16 + b_c;
                ldsm4(b[ni], sB + sw128((uint32_t)(nrow * 128 + kcol * 2)));
            }
            // interleaved issue of chunk c+1, row group kk (rows 32kk..32kk+31)
            if (pf) {
                uint32_t off = ld_off0 + (uint32_t)kk * 32 * 128;
                size_t goff = ld_g0 + (size_t)kk * 32 * DIN;
                cp16(dA + off, ga + goff);
                cp16(dB + off, gb + goff);
            }
#pragma unroll
            for (int mi = 0; mi < 4; mi++)
#pragma unroll
                for (int nj = 0; nj < 4; nj++)
                    mma16816(acc[mi][nj], a[mi], &b[nj >> 1][(nj & 1) * 2]);
        }
        if (pf) cp_commit();
    }

    // epilogue: round to fp16 (matches reference f16 z) and store
    const int g = lane >> 2, tq = lane & 3;
#pragma unroll
    for (int mi = 0; mi < 4; mi++) {
        const int r0 = m0 + wm + mi * 16 + g;
        __half* z0 = g_Zh + (size_t)r0 * MW + n0 + wn;
        __half* z1 = g_Zh + (size_t)(r0 + 8) * MW + n0 + wn;
#pragma unroll
        for (int nj = 0; nj < 4; nj++) {
            const int col = nj * 8 + tq * 2;
            *(__half2*)(z0 + col) = __floats2half2_rn(acc[mi][nj][0], acc[mi][nj][1]);
            *(__half2*)(z1 + col) = __floats2half2_rn(acc[mi][nj][2], acc[mi][nj][3]);
        }
    }
}

// kernel 4: out = fwht(Zh) * (16 * Wscale) * SV     (16 = 1024/64)
__global__ void __launch_bounds__(256) fwht_out_kernel(const float* __restrict__ SV,
                                                       const float* __restrict__ Wscale,
                                                       float* __restrict__ out) {
    __shared__ float s[4096 + 256];
    const int row = blockIdx.x;
    const int t = threadIdx.x;
    const __half* zr = g_Zh + (size_t)row * MW;
    float r[16];
#pragma unroll
    for (int q = 0; q < 2; q++) {
        uint4 u = *(const uint4*)(zr + t * 16 + q * 8);
        const __half2* h = (const __half2*)&u;
#pragma unroll
        for (int p = 0; p < 4; p++) {
            float2 f = __half22float2(h[p]);
            r[q * 8 + p * 2 + 0] = f.x;
            r[q * 8 + p * 2 + 1] = f.y;
        }
    }
    fwht16(r);
#pragma unroll
    for (int j = 0; j < 16; j++) { int i = t * 16 + j; s[PAD(i)] = r[j]; }
    __syncthreads();
    const int ilo = t & 15, ihi = t >> 4;
#pragma unroll
    for (int j = 0; j < 16; j++) { int i = ilo + 16 * j + 256 * ihi; r[j] = s[PAD(i)]; }
    fwht16(r);
#pragma unroll
    for (int j = 0; j < 16; j++) { int i = ilo + 16 * j + 256 * ihi; s[PAD(i)] = r[j]; }
    __syncthreads();
#pragma unroll
    for (int j = 0; j < 16; j++) { int i = t + 256 * j; r[j] = s[PAD(i)]; }
    fwht16(r);
    const float sc = 16.0f * Wscale[0];     // (1/64) * 1024 * Wscale
    float* orow = out + (size_t)row * MW;
#pragma unroll
    for (int j = 0; j < 16; j++)
        orow[t + 256 * j] = r[j] * sc * SV[t + 256 * j];
}

// ---------------------------------------------------------------------------
extern "C" void kernel_launch(void* const* d_in, const int* in_sizes, int n_in,
                              void* d_out, int out_size) {
    const float* input  = (const float*)d_in[0];
    const int*   Qidxs  = (const int*)d_in[1];
    const float* SU     = (const float*)d_in[2];
    const float* SV     = (const float*)d_in[3];
    const float* Wscale = (const float*)d_in[4];
    const void*  CBraw  = (const void*)d_in[5];
    float* out = (float*)d_out;

    const int gemm_smem = 4 * ATILE_BYTES;   // 65536 bytes
    cudaFuncSetAttribute(gemm_kernel, cudaFuncAttributeMaxDynamicSharedMemorySize, gemm_smem);

    fwht_in_kernel<<<ROWS, 256>>>(input, SU);
    decode_kernel<<<(MW * DIN / 4) / 256, 256>>>(Qidxs, CBraw);
    dummy_kernel<<<1, 32>>>();   // keeps ncu capture (6th launch) on gemm
    gemm_kernel<<<dim3(MW / 128, ROWS / 128), 256, gemm_smem>>>();
    fwht_out_kernel<<<ROWS, 256>>>(SV, Wscale, out);
}

// round 17
// speedup vs baseline: 1.1286x; 1.1286x over previous
#include <cuda_runtime.h>
#include <cuda_fp16.h>
#include <cstdint>

// ---------------------------------------------------------------------------
// QuantizedD4Linear on GB300 (sm_103a; harness emits compute_103 base PTX so
// tcgen05 is unavailable -> mma.sync.m16n8k16 HMMA path)
//   out = fwht( fp16( fwht(x*SU)/1024 ) @ W^T  * Wscale*1024 ) * SV
//   W[m, 4j+t] = D4_CB[Qidxs[m,j], t]
// R17: GEMM frozen at exact R12 config (best measured: 597us, tensor 76%).
//      Dummy kernel removed; decode fused into fwht_in via grid split so its
//      ~10us of traffic overlaps fwht_in's tail waves.
// ---------------------------------------------------------------------------

#define ROWS 8192   // 4*2048
#define DIN  4096   // 4*1024
#define MW   4096   // output features

// scratch (device globals: allocation-free rule)
static __device__ __half g_Xh[(size_t)ROWS * DIN];   // 64 MB fp16 activations
static __device__ __half g_W [(size_t)MW   * DIN];   // 32 MB fp16 decoded weights
static __device__ __half g_Zh[(size_t)ROWS * MW];    // 64 MB fp16 z (pre 2nd fwht)

// ---------------------------------------------------------------------------
// PTX helpers (base-ISA only: cp.async / ldmatrix / mma.sync)
// ---------------------------------------------------------------------------
static __device__ __forceinline__ uint32_t smem_u32(const void* p) {
    uint32_t a;
    asm("{ .reg .u64 t; cvta.to.shared.u64 t, %1; cvt.u32.u64 %0, t; }" : "=r"(a) : "l"(p));
    return a;
}
static __device__ __forceinline__ void cp16(uint32_t dst, const void* src) {
    asm volatile("cp.async.cg.shared.global [%0], [%1], 16;" :: "r"(dst), "l"(src) : "memory");
}
static __device__ __forceinline__ void cp_commit() {
    asm volatile("cp.async.commit_group;" ::: "memory");
}
template <int N>
static __device__ __forceinline__ void cp_wait() {
    asm volatile("cp.async.wait_group %0;" :: "n"(N) : "memory");
}
static __device__ __forceinline__ uint32_t sw128(uint32_t o) { return o ^ ((o >> 3) & 0x70); }

static __device__ __forceinline__ void ldsm4(uint32_t* r, uint32_t addr) {
    asm volatile("ldmatrix.sync.aligned.m8n8.x4.shared.b16 {%0,%1,%2,%3}, [%4];"
                 : "=r"(r[0]), "=r"(r[1]), "=r"(r[2]), "=r"(r[3]) : "r"(addr));
}
static __device__ __forceinline__ void mma16816(float* c, const uint32_t* a, const uint32_t* b) {
    asm volatile(
        "mma.sync.aligned.m16n8k16.row.col.f32.f16.f16.f32 "
        "{%0,%1,%2,%3}, {%4,%5,%6,%7}, {%8,%9}, {%0,%1,%2,%3};"
        : "+f"(c[0]), "+f"(c[1]), "+f"(c[2]), "+f"(c[3])
        : "r"(a[0]), "r"(a[1]), "r"(a[2]), "r"(a[3]), "r"(b[0]), "r"(b[1]));
}

// ---------------------------------------------------------------------------
// register-blocked FWHT helpers: 4096 = 16 x 16 x 16 radix decomposition
// ---------------------------------------------------------------------------
static __device__ __forceinline__ void fwht16(float* r) {
#pragma unroll
    for (int h = 1; h < 16; h <<= 1) {
#pragma unroll
        for (int j = 0; j < 16; j++) {
            if (!(j & h)) {
                float a = r[j], b = r[j + h];
                r[j] = a + b;
                r[j + h] = a - b;
            }
        }
    }
}
#define PAD(i) ((i) + ((i) >> 4))

// ---------------------------------------------------------------------------
// kernel 1 (fused): blocks [0, ROWS): Xh = fp16( fwht(input*SU) / 65536 )
//                   blocks [ROWS, ROWS+DECODE_BLOCKS): decode W from Qidxs
// ---------------------------------------------------------------------------
#define DECODE_BLOCKS 4096   // (MW*DIN/4 entries) / (256 thr * 4 entries/thr)

__global__ void __launch_bounds__(256) fwht_in_decode_kernel(
    const float* __restrict__ in, const float* __restrict__ SU,
    const int* __restrict__ Qidxs, const void* __restrict__ CBraw) {
    __shared__ float s[4096 + 256];
    __shared__ uint2 cb[256];
    const int t = threadIdx.x;

    if (blockIdx.x >= ROWS) {
        // ---- decode branch: 4 codebook entries per thread ----
        const uint32_t w0 = ((const uint32_t*)CBraw)[0];
        int mode;                               // 0=f16, 1=bf16, 2=f32
        if ((w0 & 0xFFFFu) == 0u) {
            mode = 2;
        } else {
            const uint32_t h = w0 & 0x7FFFu;
            mode = (h == 0x3800u || h == 0x3E00u || h == 0x4100u) ? 0 : 1;
        }
        if (mode == 0) {
            cb[t] = ((const uint2*)CBraw)[t];
        } else if (mode == 2) {
            float4 v = ((const float4*)CBraw)[t];
            __half2 lo = __floats2half2_rn(v.x, v.y);
            __half2 hi = __floats2half2_rn(v.z, v.w);
            uint2 o;
            o.x = *(const uint32_t*)&lo;
            o.y = *(const uint32_t*)&hi;
            cb[t] = o;
        } else {
            uint2 v = ((const uint2*)CBraw)[t];
            uint32_t b0 = (v.x & 0xFFFFu) << 16, b1 = (v.x & 0xFFFF0000u);
            uint32_t b2 = (v.y & 0xFFFFu) << 16, b3 = (v.y & 0xFFFF0000u);
            __half2 lo = __floats2half2_rn(__uint_as_float(b0), __uint_as_float(b1));
            __half2 hi = __floats2half2_rn(__uint_as_float(b2), __uint_as_float(b3));
            uint2 o;
            o.x = *(const uint32_t*)&lo;
            o.y = *(const uint32_t*)&hi;
            cb[t] = o;
        }
        __syncthreads();

        const int base4 = ((blockIdx.x - ROWS) * 256 + t);   // int4 index
        int4 q = ((const int4*)Qidxs)[base4];                 // 4 code indices
        uint2 w0v = cb[q.x], w1v = cb[q.y], w2v = cb[q.z], w3v = cb[q.w];
        uint4* dst = (uint4*)((uint2*)g_W + (size_t)base4 * 4);
        uint4 o0; o0.x = w0v.x; o0.y = w0v.y; o0.z = w1v.x; o0.w = w1v.y;
        uint4 o1; o1.x = w2v.x; o1.y = w2v.y; o1.z = w3v.x; o1.w = w3v.y;
        dst[0] = o0;
        dst[1] = o1;
        return;
    }

    // ---- FWHT branch (byte-identical math to R12's fwht_in) ----
    const int row = blockIdx.x;
    const float* xr = in + (size_t)row * DIN;
    float r[16];
#pragma unroll
    for (int q = 0; q < 4; q++) {
        float4 v = *(const float4*)(xr + t * 16 + q * 4);
        float4 u = *(const float4*)(SU + t * 16 + q * 4);
        r[q * 4 + 0] = v.x * u.x;
        r[q * 4 + 1] = v.y * u.y;
        r[q * 4 + 2] = v.z * u.z;
        r[q * 4 + 3] = v.w * u.w;
    }
    fwht16(r);                              // bits 0-3
#pragma unroll
    for (int j = 0; j < 16; j++) { int i = t * 16 + j; s[PAD(i)] = r[j]; }
    __syncthreads();
    const int ilo = t & 15, ihi = t >> 4;
#pragma unroll
    for (int j = 0; j < 16; j++) { int i = ilo + 16 * j + 256 * ihi; r[j] = s[PAD(i)]; }
    fwht16(r);                              // bits 4-7
#pragma unroll
    for (int j = 0; j < 16; j++) { int i = ilo + 16 * j + 256 * ihi; s[PAD(i)] = r[j]; }
    __syncthreads();
#pragma unroll
    for (int j = 0; j < 16; j++) { int i = t + 256 * j; r[j] = s[PAD(i)]; }
    fwht16(r);                              // bits 8-11
    const float sc = 1.0f / 65536.0f;       // (1/sqrt(4096)) * (1/1024)
    __half* orow = g_Xh + (size_t)row * DIN;
#pragma unroll
    for (int j = 0; j < 16; j++)
        orow[t + 256 * j] = __float2half_rn(r[j] * sc);
}

// ---------------------------------------------------------------------------
// kernel 2: HMMA GEMM  Zh = fp16( Xh @ W^T ), f32 accumulate  (exact R12)
//   BM=128, BN=128, BK=64; 8 warps, warp tile 64x32
//   double-buffered cp.async, SW128 smem (128 B rows), 2 CTAs/SM
// ---------------------------------------------------------------------------
#define BK 64
#define NITER (DIN / BK)        // 64
#define ATILE_BYTES 16384       // 128 rows * 128 B

extern __shared__ char dynsmem[];

__global__ void __launch_bounds__(256, 2) gemm_kernel() {
    const uint32_t base = smem_u32(dynsmem);
    const uint32_t aA = base;                       // [A0][A1][B0][B1], 16KB each
    const uint32_t aB = base + 2 * ATILE_BYTES;

    const int t = threadIdx.x;
    const int wid = t >> 5;
    const int lane = t & 31;
    const int wm = (wid >> 2) * 64;                 // warp m offset in tile
    const int wn = (wid & 3) * 32;                  // warp n offset in tile

    const int m0 = blockIdx.y * 128;
    const int n0 = blockIdx.x * 128;
    const __half* Ag = g_Xh + (size_t)m0 * DIN;
    const __half* Bg = g_W + (size_t)n0 * DIN;

    float acc[4][4][4];
#pragma unroll
    for (int mi = 0; mi < 4; mi++)
#pragma unroll
        for (int nj = 0; nj < 4; nj++)
#pragma unroll
            for (int q = 0; q < 4; q++) acc[mi][nj][q] = 0.0f;

    // prologue: chunk 0 -> buf 0
    {
#pragma unroll
        for (int i = 0; i < 4; i++) {
            int op = t + 256 * i;
            int row = op >> 3, seg = op & 7;
            uint32_t off = sw128((uint32_t)(row * 128 + seg * 16));
            cp16(aA + off, Ag + (size_t)row * DIN + seg * 8);
            cp16(aB + off, Bg + (size_t)row * DIN + seg * 8);
        }
        cp_commit();
    }

    // ldmatrix intra-warp address components
    const int a_r = (lane & 15);                    // A row within 16
    const int a_c = (lane >> 4) << 3;               // A col half-offset {0,8}
    const int b_r = (lane & 7) + ((lane >> 4) << 3);// B n-row within 16
    const int b_c = ((lane >> 3) & 1) << 3;         // B k-col offset {0,8}

#pragma unroll 1
    for (int c = 0; c < NITER; ++c) {
        const int buf = c & 1;

        if (c + 1 < NITER) {
            const __half* ga = Ag + (c + 1) * BK;
            const __half* gb = Bg + (c + 1) * BK;
            const uint32_t dA = aA + (buf ^ 1) * ATILE_BYTES;
            const uint32_t dB = aB + (buf ^ 1) * ATILE_BYTES;
#pragma unroll
            for (int i = 0; i < 4; i++) {
                int op = t + 256 * i;
                int row = op >> 3, seg = op & 7;
                uint32_t off = sw128((uint32_t)(row * 128 + seg * 16));
                cp16(dA + off, ga + (size_t)row * DIN + seg * 8);
                cp16(dB + off, gb + (size_t)row * DIN + seg * 8);
            }
            cp_commit();
            cp_wait<1>();                           // chunk c resident
        } else {
            cp_wait<0>();
        }
        __syncthreads();

        const uint32_t sA = aA + buf * ATILE_BYTES;
        const uint32_t sB = aB + buf * ATILE_BYTES;
#pragma unroll
        for (int kk = 0; kk < 4; kk++) {            // K16 steps within BK=64
            uint32_t a[4][4], b[2][4];
#pragma unroll
            for (int mi = 0; mi < 4; mi++) {
                int row = wm + mi * 16 + a_r;
                int col = kk * 16 + a_c;
                ldsm4(a[mi], sA + sw128((uint32_t)(row * 128 + col * 2)));
            }
#pragma unroll
            for (int ni = 0; ni < 2; ni++) {
                int nrow = wn + ni * 16 + b_r;
                int kcol = kk * 16 + b_c;
                ldsm4(b[ni], sB + sw128((uint32_t)(nrow * 128 + kcol * 2)));
            }
#pragma unroll
            for (int mi = 0; mi < 4; mi++)
#pragma unroll
                for (int nj = 0; nj < 4; nj++)
                    mma16816(acc[mi][nj], a[mi], &b[nj >> 1][(nj & 1) * 2]);
        }
        __syncthreads();                            // before overwriting buf
    }

    // epilogue: round to fp16 (matches reference f16 z) and store
    const int g = lane >> 2, tq = lane & 3;
#pragma unroll
    for (int mi = 0; mi < 4; mi++) {
        const int r0 = m0 + wm + mi * 16 + g;
        __half* z0 = g_Zh + (size_t)r0 * MW + n0 + wn;
        __half* z1 = g_Zh + (size_t)(r0 + 8) * MW + n0 + wn;
#pragma unroll
        for (int nj = 0; nj < 4; nj++) {
            const int col = nj * 8 + tq * 2;
            *(__half2*)(z0 + col) = __floats2half2_rn(acc[mi][nj][0], acc[mi][nj][1]);
            *(__half2*)(z1 + col) = __floats2half2_rn(acc[mi][nj][2], acc[mi][nj][3]);
        }
    }
}

// kernel 3: out = fwht(Zh) * (16 * Wscale) * SV     (16 = 1024/64)
__global__ void __launch_bounds__(256) fwht_out_kernel(const float* __restrict__ SV,
                                                       const float* __restrict__ Wscale,
                                                       float* __restrict__ out) {
    __shared__ float s[4096 + 256];
    const int row = blockIdx.x;
    const int t = threadIdx.x;
    const __half* zr = g_Zh + (size_t)row * MW;
    float r[16];
#pragma unroll
    for (int q = 0; q < 2; q++) {
        uint4 u = *(const uint4*)(zr + t * 16 + q * 8);
        const __half2* h = (const __half2*)&u;
#pragma unroll
        for (int p = 0; p < 4; p++) {
            float2 f = __half22float2(h[p]);
            r[q * 8 + p * 2 + 0] = f.x;
            r[q * 8 + p * 2 + 1] = f.y;
        }
    }
    fwht16(r);
#pragma unroll
    for (int j = 0; j < 16; j++) { int i = t * 16 + j; s[PAD(i)] = r[j]; }
    __syncthreads();
    const int ilo = t & 15, ihi = t >> 4;
#pragma unroll
    for (int j = 0; j < 16; j++) { int i = ilo + 16 * j + 256 * ihi; r[j] = s[PAD(i)]; }
    fwht16(r);
#pragma unroll
    for (int j = 0; j < 16; j++) { int i = ilo + 16 * j + 256 * ihi; s[PAD(i)] = r[j]; }
    __syncthreads();
#pragma unroll
    for (int j = 0; j < 16; j++) { int i = t + 256 * j; r[j] = s[PAD(i)]; }
    fwht16(r);
    const float sc = 16.0f * Wscale[0];     // (1/64) * 1024 * Wscale
    float* orow = out + (size_t)row * MW;
#pragma unroll
    for (int j = 0; j < 16; j++)
        orow[t + 256 * j] = r[j] * sc * SV[t + 256 * j];
}

// ---------------------------------------------------------------------------
extern "C" void kernel_launch(void* const* d_in, const int* in_sizes, int n_in,
                              void* d_out, int out_size) {
    const float* input  = (const float*)d_in[0];
    const int*   Qidxs  = (const int*)d_in[1];
    const float* SU     = (const float*)d_in[2];
    const float* SV     = (const float*)d_in[3];
    const float* Wscale = (const float*)d_in[4];
    const void*  CBraw  = (const void*)d_in[5];
    float* out = (float*)d_out;

    const int gemm_smem = 4 * ATILE_BYTES;   // 65536 bytes
    cudaFuncSetAttribute(gemm_kernel, cudaFuncAttributeMaxDynamicSharedMemorySize, gemm_smem);

    fwht_in_decode_kernel<<<ROWS + DECODE_BLOCKS, 256>>>(input, SU, Qidxs, CBraw);
    gemm_kernel<<<dim3(MW / 128, ROWS / 128), 256, gemm_smem>>>();
    fwht_out_kernel<<<ROWS, 256>>>(SV, Wscale, out);
}